// round 15
// baseline (speedup 1.0000x reference)
#include <cuda_runtime.h>

#define BATCH 32
#define IN_H  128
#define IN_W  512
#define CHAN  32
#define OUT_H 64
#define OUT_W 256

// Warp-autonomous scheme: no shared memory, no __syncthreads.
// Each warp handles 4 consecutive-wx output points (8 lanes per point,
// float4 channel group per lane).
//   1) lanes 0..3 compute the 4 points' weights + tap indices (predicated)
//   2) 8 warp shuffles broadcast {wA..wD, iA..iD} (src lane = lane>>3)
//   3) 4 LDG.128 gathers + 16 FFMA blend + 1 STG.128 store
// Warps are fully independent -> the SM scheduler always has issuable
// warps; no barrier/phase bubbles.
// Grid: 524288 points / 4 per warp / 8 warps per CTA = 16384 CTAs x 256.

__global__ void __launch_bounds__(256, 8)
stn_bilinear_kernel(const float* __restrict__ image,
                    const float* __restrict__ theta,
                    float* __restrict__ out)
{
    const unsigned tid  = threadIdx.x;
    const unsigned lane = tid & 31u;
    const unsigned n0   = (blockIdx.x * 8u + (tid >> 5)) * 4u;  // first of 4 points

    float    wAr = 0.f, wBr = 0.f, wCr = 0.f, wDr = 0.f;
    unsigned iAr = 0u, iBr = 0u, iCr = 0u, iDr = 0u;

    if (lane < 4u) {
        const unsigned n  = n0 + lane;
        const unsigned wx = n & 255u;          // OUT_W = 256
        const unsigned r  = n >> 8;
        const unsigned hy = r & 63u;           // OUT_H = 64
        const unsigned b  = r >> 6;

        const float xg = (float)wx * (2.0f / 255.0f) - 1.0f;
        const float yg = (float)hy * (2.0f / 63.0f) - 1.0f;

        // theta[b] 2x3; reference hack: zero row 1 of batch 0, row 0 of batch 1
        const float* th = theta + b * 6u;
        float t00 = __ldg(th + 0), t01 = __ldg(th + 1), t02 = __ldg(th + 2);
        float t10 = __ldg(th + 3), t11 = __ldg(th + 4), t12 = __ldg(th + 5);
        if (b == 0u) { t10 = 0.0f; t11 = 0.0f; t12 = 0.0f; }
        if (b == 1u) { t00 = 0.0f; t01 = 0.0f; t02 = 0.0f; }

        float cx = t00 * xg + t01 * yg + t02;
        float cy = t10 * xg + t11 * yg + t12;

        float x = 0.5f * (cx + 1.0f) * (float)IN_W;   // uses W, not W-1
        float y = 0.5f * (cy + 1.0f) * (float)IN_H;

        int x0 = (int)x;                              // trunc toward zero
        int y0 = (int)y;
        int x1 = x0 + 1;
        int y1 = y0 + 1;
        x0 = min(max(x0, 0), IN_W - 1);               // clip BEFORE weights
        x1 = min(max(x1, 0), IN_W - 1);
        y0 = min(max(y0, 0), IN_H - 1);
        y1 = min(max(y1, 0), IN_H - 1);

        float x0f = (float)x0, x1f = (float)x1;
        float y0f = (float)y0, y1f = (float)y1;

        wAr = (x1f - x) * (y1f - y);
        wBr = (x1f - x) * (y - y0f);
        wCr = (x - x0f) * (y1f - y);
        wDr = (x - x0f) * (y - y0f);

        const unsigned basePix = b * (unsigned)(IN_H * IN_W);
        const unsigned row0 = basePix + (unsigned)y0 * (unsigned)IN_W;
        const unsigned row1 = basePix + (unsigned)y1 * (unsigned)IN_W;
        iAr = (row0 + (unsigned)x0) << 3;   // float4 units
        iBr = (row1 + (unsigned)x0) << 3;
        iCr = (row0 + (unsigned)x1) << 3;
        iDr = (row1 + (unsigned)x1) << 3;
    }

    // Broadcast params of point p = lane>>3 from lane p
    const int src = (int)(lane >> 3);
    const float    wA = __shfl_sync(0xffffffffu, wAr, src);
    const float    wB = __shfl_sync(0xffffffffu, wBr, src);
    const float    wC = __shfl_sync(0xffffffffu, wCr, src);
    const float    wD = __shfl_sync(0xffffffffu, wDr, src);
    const unsigned iA = __shfl_sync(0xffffffffu, iAr, src);
    const unsigned iB = __shfl_sync(0xffffffffu, iBr, src);
    const unsigned iC = __shfl_sync(0xffffffffu, iCr, src);
    const unsigned iD = __shfl_sync(0xffffffffu, iDr, src);

    const unsigned cg = lane & 7u;
    const float4* __restrict__ img4 = (const float4*)image;

    float4 pA = __ldg(img4 + (iA + cg));
    float4 pB = __ldg(img4 + (iB + cg));
    float4 pC = __ldg(img4 + (iC + cg));
    float4 pD = __ldg(img4 + (iD + cg));

    float4 res;
    res.x = pA.x * wA + pB.x * wB + pC.x * wC + pD.x * wD;
    res.y = pA.y * wA + pB.y * wB + pC.y * wC + pD.y * wD;
    res.z = pA.z * wA + pB.z * wB + pC.z * wC + pD.z * wD;
    res.w = pA.w * wA + pB.w * wB + pC.w * wC + pD.w * wD;

    // Warp's 32 lanes cover points n0..n0+3 x 8 channel groups: one
    // contiguous 512B STG.128.
    float4* __restrict__ out4 = (float4*)out;
    __stcg(&out4[(n0 << 3) + (lane & 31u)], res);
}

extern "C" void kernel_launch(void* const* d_in, const int* in_sizes, int n_in,
                              void* d_out, int out_size)
{
    const float* image = (const float*)d_in[0];
    const float* theta = (const float*)d_in[1];
    float*       out   = (float*)d_out;

    stn_bilinear_kernel<<<16384, 256>>>(image, theta, out);
}

// round 16
// speedup vs baseline: 1.1622x; 1.1622x over previous
#include <cuda_runtime.h>

#define BATCH 32
#define IN_H  128
#define IN_W  512
#define CHAN  32
#define OUT_H 64
#define OUT_W 256

// Warp-autonomous with smem broadcast (no shuffles, no __syncthreads).
// Each warp owns 8 consecutive output points (same b, hy; wx..wx+7):
//   1) lanes 0..7 compute the 8 points' weights + tap indices into the
//      warp's private smem slice (predicated, one pass)
//   2) __syncwarp()
//   3) phase 2 exactly like R8: 8 threads per point (float4 channel group),
//      2 points per thread, 4 LDG.128 gathers + blend + __stcg per point.
// Block = 256 threads = 8 warps = 64 points. Grid = 8192 blocks.
// Warps never wait on each other -> no barrier bubbles.

struct PParam {
    float    wA, wB, wC, wD;
    unsigned iA, iB, iC, iD;   // pixel index * 8 (float4 units), without cg
};

__global__ void __launch_bounds__(256, 8)
stn_bilinear_kernel(const float* __restrict__ image,
                    const float* __restrict__ theta,
                    float* __restrict__ out)
{
    __shared__ PParam sp[64];

    const unsigned tid  = threadIdx.x;
    const unsigned lane = tid & 31u;
    const unsigned w    = tid >> 5;                    // warp 0..7
    const unsigned base = (blockIdx.x * 8u + w) * 8u;  // warp's first point

    // ---- lanes 0..7: params for the warp's 8 points ----
    if (lane < 8u) {
        const unsigned n  = base + lane;
        const unsigned wx = n & 255u;          // OUT_W = 256
        const unsigned r  = n >> 8;
        const unsigned hy = r & 63u;           // OUT_H = 64
        const unsigned b  = r >> 6;

        const float xg = (float)wx * (2.0f / 255.0f) - 1.0f;
        const float yg = (float)hy * (2.0f / 63.0f) - 1.0f;

        // theta[b] 2x3; reference hack: zero row 1 of batch 0, row 0 of batch 1
        const float* th = theta + b * 6u;
        float t00 = __ldg(th + 0), t01 = __ldg(th + 1), t02 = __ldg(th + 2);
        float t10 = __ldg(th + 3), t11 = __ldg(th + 4), t12 = __ldg(th + 5);
        if (b == 0u) { t10 = 0.0f; t11 = 0.0f; t12 = 0.0f; }
        if (b == 1u) { t00 = 0.0f; t01 = 0.0f; t02 = 0.0f; }

        float cx = t00 * xg + t01 * yg + t02;
        float cy = t10 * xg + t11 * yg + t12;

        float x = 0.5f * (cx + 1.0f) * (float)IN_W;   // uses W, not W-1
        float y = 0.5f * (cy + 1.0f) * (float)IN_H;

        int x0 = (int)x;                              // trunc toward zero
        int y0 = (int)y;
        int x1 = x0 + 1;
        int y1 = y0 + 1;
        x0 = min(max(x0, 0), IN_W - 1);               // clip BEFORE weights
        x1 = min(max(x1, 0), IN_W - 1);
        y0 = min(max(y0, 0), IN_H - 1);
        y1 = min(max(y1, 0), IN_H - 1);

        float x0f = (float)x0, x1f = (float)x1;
        float y0f = (float)y0, y1f = (float)y1;

        PParam pp;
        pp.wA = (x1f - x) * (y1f - y);
        pp.wB = (x1f - x) * (y - y0f);
        pp.wC = (x - x0f) * (y1f - y);
        pp.wD = (x - x0f) * (y - y0f);

        const unsigned basePix = b * (unsigned)(IN_H * IN_W);
        const unsigned row0 = basePix + (unsigned)y0 * (unsigned)IN_W;
        const unsigned row1 = basePix + (unsigned)y1 * (unsigned)IN_W;
        pp.iA = (row0 + (unsigned)x0) << 3;
        pp.iB = (row1 + (unsigned)x0) << 3;
        pp.iC = (row0 + (unsigned)x1) << 3;
        pp.iD = (row1 + (unsigned)x1) << 3;

        sp[w * 8u + lane] = pp;
    }
    __syncwarp();

    // ---- phase 2: 8 threads per point, 2 points per thread ----
    const unsigned cg = lane & 7u;
    const unsigned q  = lane >> 3;       // 0..3

    const float4* __restrict__ img4 = (const float4*)image;
    float4* __restrict__ out4 = (float4*)out;

    #pragma unroll
    for (int half = 0; half < 2; ++half) {
        const unsigned pi = (unsigned)half * 4u + q;      // 0..7 within warp
        const PParam pp = sp[w * 8u + pi];

        float4 pA = __ldg(img4 + (pp.iA + cg));
        float4 pB = __ldg(img4 + (pp.iB + cg));
        float4 pC = __ldg(img4 + (pp.iC + cg));
        float4 pD = __ldg(img4 + (pp.iD + cg));

        float4 res;
        res.x = pA.x * pp.wA + pB.x * pp.wB + pC.x * pp.wC + pD.x * pp.wD;
        res.y = pA.y * pp.wA + pB.y * pp.wB + pC.y * pp.wC + pD.y * pp.wD;
        res.z = pA.z * pp.wA + pB.z * pp.wB + pC.z * pp.wC + pD.z * pp.wD;
        res.w = pA.w * pp.wA + pB.w * pp.wB + pC.w * pp.wC + pD.w * pp.wD;

        // points base..base+7 are consecutive wx of one output row:
        // flat out index = n*32 + c  -> float4 index = n*8 + cg
        const unsigned n = base + pi;
        __stcg(&out4[(n << 3) + cg], res);
    }
}

extern "C" void kernel_launch(void* const* d_in, const int* in_sizes, int n_in,
                              void* d_out, int out_size)
{
    const float* image = (const float*)d_in[0];
    const float* theta = (const float*)d_in[1];
    float*       out   = (float*)d_out;

    stn_bilinear_kernel<<<8192, 256>>>(image, theta, out);
}